// round 16
// baseline (speedup 1.0000x reference)
#include <cuda_runtime.h>
#include <cuda_fp16.h>
#include <math.h>
#include <stdint.h>

#define DEV_INLINE __device__ __forceinline__

#define B_    16
#define S_    2048
#define D_    512
#define H_    2048
#define L_    4
#define M_    64
#define NTOK  (B_ * S_)
#define NCH   4                               // S-split chunks for kv pipeline

typedef __half  f16;

// ---------------- scratch ----------------
__device__ float g_h  [NTOK * D_];
__device__ f16   g_ha [NTOK * D_];
__device__ float g_pqk[NTOK * 128];                // stride 128: pq 0:64, pk 64:128 (layer3: stride 64)
__device__ float g_kvpart[NCH * B_ * M_ * D_];     // S-split partials of G
__device__ float g_kv [B_ * M_ * D_];
__device__ float g_pks[B_ * M_];
__device__ float g_pkpart[B_ * NCH * M_];
__device__ f16   g_at [NTOK * D_];
__device__ float g_w  [NTOK * D_];
__device__ f16   g_ln [NTOK * D_];
__device__ f16   g_ff [NTOK * H_];
__device__ float g_s0 [B_ * D_], g_s1 [B_ * D_], g_s2 [B_ * M_], g_s3 [B_ * D_], g_sff[B_ * H_];
__device__ float g_T   [L_ * 2 * D_ * M_];
__device__ f16   g_PQKh[L_ * 128 * D_], g_PQKl[L_ * 128 * D_];
__device__ float g_bPQK[L_ * 128];
__device__ f16 g_Woh[L_*D_*D_], g_Wolo[L_*D_*D_];
__device__ f16 g_W1h[L_*H_*D_], g_W1lo[L_*H_*D_];
__device__ f16 g_W2h[L_*D_*H_], g_W2lo[L_*D_*H_];

// ---------------- helpers ----------------
DEV_INLINE uint32_t smem_u32(const void* p) {
    uint32_t a;
    asm("{ .reg .u64 t; cvta.to.shared.u64 t, %1; cvt.u32.u64 %0, t; }" : "=r"(a) : "l"(p));
    return a;
}
DEV_INLINE void cp16(uint32_t dst, const void* src) {
    asm volatile("cp.async.cg.shared.global [%0], [%1], 16;"
                 :: "r"(dst), "l"(__cvta_generic_to_global(src)));
}
DEV_INLINE void cp_commit() { asm volatile("cp.async.commit_group;"); }
template<int N> DEV_INLINE void cp_wait() {
    asm volatile("cp.async.wait_group %0;" :: "n"(N) : "memory");
}
DEV_INLINE void ldm_x4(uint32_t& r0, uint32_t& r1, uint32_t& r2, uint32_t& r3, uint32_t addr) {
    asm volatile("ldmatrix.sync.aligned.m8n8.x4.shared.b16 {%0,%1,%2,%3}, [%4];"
                 : "=r"(r0), "=r"(r1), "=r"(r2), "=r"(r3) : "r"(addr));
}
DEV_INLINE void mma16816(float* d, const uint32_t* a, const uint32_t* b) {
    asm volatile("mma.sync.aligned.m16n8k16.row.col.f32.f16.f16.f32 "
                 "{%0,%1,%2,%3}, {%4,%5,%6,%7}, {%8,%9}, {%0,%1,%2,%3};"
                 : "+f"(d[0]), "+f"(d[1]), "+f"(d[2]), "+f"(d[3])
                 : "r"(a[0]), "r"(a[1]), "r"(a[2]), "r"(a[3]), "r"(b[0]), "r"(b[1]));
}
DEV_INLINE void split_f16(float v, f16& h, f16& l) {
    h = __float2half_rn(v);
    l = __float2half_rn(v - __half2float(h));
}
DEV_INLINE void st_h2(f16* C, size_t o, float x, float y) {
    *reinterpret_cast<__half2*>(C + o) = __floats2half2_rn(x, y);
}
DEV_INLINE unsigned long long pack_dup(float a) {
    unsigned long long r;
    asm("mov.b64 %0, {%1, %2};" : "=l"(r) : "f"(a), "f"(a));
    return r;
}
DEV_INLINE void ffma2(unsigned long long& d, unsigned long long a, unsigned long long b) {
    asm("fma.rn.f32x2 %0, %1, %2, %0;" : "+l"(d) : "l"(a), "l"(b));
}
DEV_INLINE float2 unpack2(unsigned long long v) {
    float2 f;
    asm("mov.b64 {%0, %1}, %2;" : "=f"(f.x), "=f"(f.y) : "l"(v));
    return f;
}

enum { ACT_NONE = 0, ACT_ELU1 = 1, ACT_GELU = 2 };

// ========== fp16 2-MMA split GEMM, BM=256, 512 threads, single-sync ==========
template<int BN, int ACT, bool HAS_BIAS, bool ADD_RES, bool OUT_F32, bool OUT_F16>
__global__ void __launch_bounds__(512, 1)
mma_gemm_kernel(const f16* __restrict__ A, const f16* __restrict__ Bh,
                const f16* __restrict__ Bl, const float* __restrict__ bias,
                const float* __restrict__ res,
                float* __restrict__ Cf, f16* __restrict__ Ch,
                int M, int N, int K)
{
    constexpr int SA    = 72;
    constexpr int ABYT  = 256 * SA * 2;           // A tile bytes (256 rows)
    constexpr int BBYT  = BN * SA * 2;            // one B matrix
    constexpr int STAGE = ABYT + 2 * BBYT;
    constexpr int WN = BN / 4, NT = WN / 8, NG = WN / 16;

    extern __shared__ __align__(16) char smem[];
    const int tid  = threadIdx.x;                 // 512
    const int wid  = tid >> 5;                    // 0..15
    const int lane = tid & 31;
    const int bm   = blockIdx.y * 256;
    const int bn   = blockIdx.x * BN;
    const int wm   = (wid >> 2) * 64;             // 0,64,128,192
    const int wn   = (wid & 3) * WN;

    float acc[4][NT][4];
#pragma unroll
    for (int i = 0; i < 4; i++)
#pragma unroll
        for (int j = 0; j < NT; j++)
#pragma unroll
            for (int q = 0; q < 4; q++) acc[i][j][q] = 0.f;

    const uint32_t smb = smem_u32(smem);
    auto load_stage = [&](int c, int s) {
        const size_t ko = (size_t)c * 64;
        const uint32_t base = smb + (uint32_t)s * STAGE;
#pragma unroll
        for (int i = 0; i < 4; i++) {                 // A: 256 rows x 8 segs / 512 thr
            int idx = tid + i * 512;
            int r = idx >> 3, cs = idx & 7;
            cp16(base + (uint32_t)(r * SA + cs * 8) * 2,
                 A + (size_t)(bm + r) * K + ko + cs * 8);
        }
#pragma unroll
        for (int i = 0; i < BN * 8 / 512; i++) {      // B hi + lo
            int idx = tid + i * 512;
            int r = idx >> 3, cs = idx & 7;
            uint32_t off = (uint32_t)(r * SA + cs * 8) * 2;
            const size_t go = (size_t)(bn + r) * K + ko + cs * 8;
            cp16(base + ABYT + off,        Bh + go);
            cp16(base + ABYT + BBYT + off, Bl + go);
        }
        cp_commit();
    };

    const int C_ = K >> 6;
    load_stage(0, 0);

    const int arow  = (lane & 15);
    const int acol8 = (lane >> 4) * 8;
    const int brow  = (lane & 7) + ((lane >> 4) & 1) * 8;
    const int bcol8 = ((lane >> 3) & 1) * 8;

    for (int c = 0; c < C_; c++) {
        cp_wait<0>();          // stage c resident
        __syncthreads();       // publishes stage c AND retires reads of slot (c+1)&1
        if (c + 1 < C_) load_stage(c + 1, (c + 1) & 1);

        const uint32_t a_base  = smb + (uint32_t)(c & 1) * STAGE;
        const uint32_t bh_base = a_base + ABYT;
        const uint32_t bl_base = bh_base + BBYT;

#pragma unroll
        for (int kk = 0; kk < 4; kk++) {
            uint32_t ar[4][4];
#pragma unroll
            for (int mi = 0; mi < 4; mi++) {
                uint32_t off = (uint32_t)((wm + mi * 16 + arow) * SA + kk * 16 + acol8) * 2;
                ldm_x4(ar[mi][0], ar[mi][1], ar[mi][2], ar[mi][3], a_base + off);
            }
            uint32_t bh[NT][2], bl[NT][2];
#pragma unroll
            for (int g = 0; g < NG; g++) {
                uint32_t off = (uint32_t)((wn + g * 16 + brow) * SA + kk * 16 + bcol8) * 2;
                uint32_t r0, r1, r2, r3;
                ldm_x4(r0, r1, r2, r3, bh_base + off);
                bh[2*g][0] = r0; bh[2*g][1] = r1; bh[2*g+1][0] = r2; bh[2*g+1][1] = r3;
                ldm_x4(r0, r1, r2, r3, bl_base + off);
                bl[2*g][0] = r0; bl[2*g][1] = r1; bl[2*g+1][0] = r2; bl[2*g+1][1] = r3;
            }
#pragma unroll
            for (int mi = 0; mi < 4; mi++)
#pragma unroll
                for (int nt = 0; nt < NT; nt++) {
                    mma16816(acc[mi][nt], ar[mi], bh[nt]);
                    mma16816(acc[mi][nt], ar[mi], bl[nt]);
                }
        }
    }

    const int rbase = bm + wm + (lane >> 2);
    const int cbase = bn + wn + (lane & 3) * 2;
#pragma unroll
    for (int mi = 0; mi < 4; mi++) {
#pragma unroll
        for (int nt = 0; nt < NT; nt++) {
            const int col = cbase + nt * 8;
            float bx = 0.f, by = 0.f;
            if (HAS_BIAS) { bx = __ldg(bias + col); by = __ldg(bias + col + 1); }
#pragma unroll
            for (int half = 0; half < 2; half++) {
                const int row = rbase + mi * 16 + half * 8;
                float vx = acc[mi][nt][half * 2 + 0] + bx;
                float vy = acc[mi][nt][half * 2 + 1] + by;
                if (ACT == ACT_ELU1) {
                    vx = (vx > 0.f) ? vx + 1.f : expf(vx);
                    vy = (vy > 0.f) ? vy + 1.f : expf(vy);
                } else if (ACT == ACT_GELU) {
                    vx = 0.5f * vx * (1.f + erff(vx * 0.70710678118654752f));
                    vy = 0.5f * vy * (1.f + erff(vy * 0.70710678118654752f));
                }
                const size_t ro = (size_t)row * N + col;
                if (ADD_RES) {
                    float2 rr = *reinterpret_cast<const float2*>(res + ro);
                    vx += rr.x; vy += rr.y;
                }
                if (OUT_F32)
                    *reinterpret_cast<float2*>(Cf + ro) = make_float2(vx, vy);
                if (OUT_F16)
                    st_h2(Ch, ro, vx, vy);
            }
        }
    }
}

template<int BN, int ACT, bool HB, bool AR, bool OF, bool OH>
static void tcg(const f16* A, const f16* Bh, const f16* Bl, const float* bias,
                const float* res, float* Cf, f16* Ch, int M, int N, int K)
{
    constexpr int STAGE = (256 * 72 * 2) + 2 * (BN * 72 * 2);
    size_t sm = 2 * (size_t)STAGE;
    auto k = mma_gemm_kernel<BN, ACT, HB, AR, OF, OH>;
    cudaFuncSetAttribute(k, cudaFuncAttributeMaxDynamicSharedMemorySize, (int)sm);
    k<<<dim3(N / BN, M / 256), 512, sm>>>(A, Bh, Bl, bias, res, Cf, Ch, M, N, K);
}

// ============ weight transpose+split ============
__global__ void wsplit_kernel(const float* __restrict__ W, int K, int N,
                              f16* __restrict__ Wh, f16* __restrict__ Wl)
{
    __shared__ float tile[32][33];
    const int l = blockIdx.z;
    const float* Ws = W + (size_t)l * K * N;
    f16* Whd = Wh + (size_t)l * N * K;
    f16* Wld = Wl + (size_t)l * N * K;
    const int n0 = blockIdx.x * 32, k0 = blockIdx.y * 32;
    const int tx = threadIdx.x, ty = threadIdx.y;
#pragma unroll
    for (int i = 0; i < 4; i++)
        tile[ty + i * 8][tx] = Ws[(size_t)(k0 + ty + i * 8) * N + n0 + tx];
    __syncthreads();
#pragma unroll
    for (int i = 0; i < 4; i++) {
        float v = tile[tx][ty + i * 8];
        f16 h, lo; split_f16(v, h, lo);
        size_t o = (size_t)(n0 + ty + i * 8) * K + k0 + tx;
        Whd[o] = h; Wld[o] = lo;
    }
}

__global__ void wsplit2_kernel(const float* __restrict__ T,
                               f16* __restrict__ Wh, f16* __restrict__ Wl)
{
    __shared__ float tile[32][33];
    const int z = blockIdx.z;
    const float* Ws = T + (size_t)z * D_ * M_;
    const size_t ob = (size_t)(z >> 1) * (128 * D_) + (size_t)(z & 1) * 64 * D_;
    f16* Whd = Wh + ob;
    f16* Wld = Wl + ob;
    const int n0 = blockIdx.x * 32, k0 = blockIdx.y * 32;
    const int tx = threadIdx.x, ty = threadIdx.y;
#pragma unroll
    for (int i = 0; i < 4; i++)
        tile[ty + i * 8][tx] = Ws[(size_t)(k0 + ty + i * 8) * M_ + n0 + tx];
    __syncthreads();
#pragma unroll
    for (int i = 0; i < 4; i++) {
        float v = tile[tx][ty + i * 8];
        f16 h, lo; split_f16(v, h, lo);
        size_t o = (size_t)(n0 + ty + i * 8) * D_ + k0 + tx;
        Whd[o] = h; Wld[o] = lo;
    }
}

// ============ fold Wq@P / Wk@P ============
__global__ void foldP_kernel(const float* __restrict__ Wq, const float* __restrict__ Wk,
                             const float* __restrict__ P, float* __restrict__ T)
{
    const int dblk = blockIdx.x;
    const int sel  = blockIdx.y;
    const int l    = blockIdx.z;
    const float* W  = (sel ? Wk : Wq) + (size_t)l * D_ * D_;
    const float* Pl = P + (size_t)l * D_ * M_;
    __shared__ float sW[64][65];
    __shared__ float sP[64][64];
    const int tid = threadIdx.x;
    const int tr = tid >> 4, tc = tid & 15;
    float acc[4][4] = {};
    for (int e0 = 0; e0 < D_; e0 += 64) {
#pragma unroll
        for (int i = 0; i < 16; i++) {
            int idx = tid + i * 256;
            int r = idx >> 6, c = idx & 63;
            sW[r][c] = W[(size_t)(dblk * 64 + r) * D_ + e0 + c];
            sP[r][c] = Pl[(size_t)(e0 + r) * M_ + c];
        }
        __syncthreads();
#pragma unroll 16
        for (int e = 0; e < 64; e++) {
            float pv[4];
#pragma unroll
            for (int j = 0; j < 4; j++) pv[j] = sP[e][tc * 4 + j];
#pragma unroll
            for (int i = 0; i < 4; i++) {
                float wv = sW[tr * 4 + i][e];
#pragma unroll
                for (int j = 0; j < 4; j++) acc[i][j] = fmaf(wv, pv[j], acc[i][j]);
            }
        }
        __syncthreads();
    }
    float* Tout = T + (size_t)(l * 2 + sel) * D_ * M_;
#pragma unroll
    for (int i = 0; i < 4; i++)
#pragma unroll
        for (int j = 0; j < 4; j++)
            Tout[(size_t)(dblk * 64 + tr * 4 + i) * M_ + tc * 4 + j] = acc[i][j];
}

__global__ void bfold_kernel(const float* __restrict__ bq, const float* __restrict__ bk,
                             const float* __restrict__ P, float* __restrict__ bPQK)
{
    const int l = blockIdx.x, sel = blockIdx.y, m = threadIdx.x;
    const float* b  = (sel ? bk : bq) + (size_t)l * D_;
    const float* Pl = P + (size_t)l * D_ * M_;
    float s = 0.f;
    for (int d = 0; d < D_; d++) s = fmaf(b[d], Pl[(size_t)d * M_ + m], s);
    bPQK[l * 128 + sel * 64 + m] = s;
}

// ================= fp32 FFMA2 SGEMM (+outer epilogue, +NCH-way A sum) =================
template <int BM, int BN, int BK, int TM, int TN, int ACT, bool HAS_BIAS, bool ADD_RES,
          bool ADD_OUTER, bool A_SUM>
__global__ void __launch_bounds__((BM / TM) * (BN / TN))
gemm_kernel(const float* __restrict__ A, const float* __restrict__ Bw,
            const float* __restrict__ bias, const float* __restrict__ res,
            float* __restrict__ C, int M, int N, int K,
            const float* __restrict__ rowscale, const float* __restrict__ colvec)
{
    constexpr int THREADS = (BM / TM) * (BN / TN);
    __shared__ __align__(16) float As[BK][BM];
    __shared__ __align__(16) float Bs[BK][BN];
    const int bm = blockIdx.y * BM, bn = blockIdx.x * BN, tid = threadIdx.x;
    constexpr int TCOLS = BN / TN;
    const int tc = tid % TCOLS, tr = tid / TCOLS;
    unsigned long long acc[TM][TN / 2];
#pragma unroll
    for (int i = 0; i < TM; i++)
#pragma unroll
        for (int j = 0; j < TN / 2; j++) acc[i][j] = 0ull;
    for (int k0 = 0; k0 < K; k0 += BK) {
        for (int i = tid; i < BM * BK / 4; i += THREADS) {
            int r = i / (BK / 4), kc = (i % (BK / 4)) * 4, gr = bm + r;
            float4 v4 = make_float4(0.f, 0.f, 0.f, 0.f);
            if (gr < M) {
                if (A_SUM) {
#pragma unroll
                    for (int ch = 0; ch < NCH; ch++) {
                        float4 p = *reinterpret_cast<const float4*>(
                            A + (size_t)ch * (B_ * M_ * D_) + (size_t)gr * K + k0 + kc);
                        v4.x += p.x; v4.y += p.y; v4.z += p.z; v4.w += p.w;
                    }
                } else {
                    v4 = *reinterpret_cast<const float4*>(A + (size_t)gr * K + k0 + kc);
                }
            }
            As[kc][r] = v4.x; As[kc+1][r] = v4.y; As[kc+2][r] = v4.z; As[kc+3][r] = v4.w;
        }
        for (int i = tid; i < BK * BN / 4; i += THREADS) {
            int r = i / (BN / 4), c = (i % (BN / 4)) * 4;
            *reinterpret_cast<float4*>(&Bs[r][c]) =
                *reinterpret_cast<const float4*>(Bw + (size_t)(k0 + r) * N + bn + c);
        }
        __syncthreads();
#pragma unroll
        for (int kk = 0; kk < BK; kk++) {
            unsigned long long ar[TM], br[TN / 2];
#pragma unroll
            for (int i = 0; i < TM; i++) ar[i] = pack_dup(As[kk][tr * TM + i]);
#pragma unroll
            for (int j = 0; j < TN / 2; j++)
                br[j] = *reinterpret_cast<const unsigned long long*>(&Bs[kk][tc * TN + 2 * j]);
#pragma unroll
            for (int i = 0; i < TM; i++)
#pragma unroll
                for (int j = 0; j < TN / 2; j++) ffma2(acc[i][j], ar[i], br[j]);
        }
        __syncthreads();
    }
#pragma unroll
    for (int i = 0; i < TM; i++) {
        int gr = bm + tr * TM + i;
        if (gr >= M) continue;
        float rs = 0.f;
        if (ADD_OUTER) rs = __ldg(rowscale + gr);
#pragma unroll
        for (int j = 0; j < TN / 2; j++) {
            int gc = bn + tc * TN + 2 * j;
            float2 v = unpack2(acc[i][j]);
            if (HAS_BIAS) { v.x += bias[gc]; v.y += bias[gc + 1]; }
            if (ADD_OUTER) {
                v.x += rs * __ldg(colvec + gc);
                v.y += rs * __ldg(colvec + gc + 1);
            }
            if (ACT == ACT_ELU1) {
                v.x = (v.x > 0.f) ? v.x + 1.f : expf(v.x);
                v.y = (v.y > 0.f) ? v.y + 1.f : expf(v.y);
            } else if (ACT == ACT_GELU) {
                v.x = 0.5f * v.x * (1.f + erff(v.x * 0.70710678118654752f));
                v.y = 0.5f * v.y * (1.f + erff(v.y * 0.70710678118654752f));
            }
            if (ADD_RES) {
                float2 rv = *reinterpret_cast<const float2*>(res + (size_t)gr * N + gc);
                v.x += rv.x; v.y += rv.y;
            }
            *reinterpret_cast<float2*>(C + (size_t)gr * N + gc) = v;
        }
    }
}

template <int ACT, bool HB, bool AR>
static void gemm128(const float* A, const float* Bw, const float* bias, const float* res,
                    float* C, int M, int N, int K)
{
    dim3 grid(N / 128, (M + 127) / 128);
    gemm_kernel<128, 128, 16, 8, 8, ACT, HB, AR, false, false><<<grid, 256>>>(
        A, Bw, bias, res, C, M, N, K, nullptr, nullptr);
}
template <int ACT>
static void gemm64n(const float* A, const float* Bw, float* C, int M, int K)
{
    dim3 grid(1, (M + 127) / 128);
    gemm_kernel<128, 64, 16, 8, 8, ACT, false, false, false, false><<<grid, 128>>>(
        A, Bw, nullptr, nullptr, C, M, 64, K, nullptr, nullptr);
}
static void gemm_outer(const float* part, const float* Wv, const float* pks, const float* bv,
                       float* kv)
{
    dim3 grid(D_ / 64, B_ * M_ / 64);
    gemm_kernel<64, 64, 16, 4, 4, ACT_NONE, false, false, true, true><<<grid, 256>>>(
        part, Wv, nullptr, nullptr, kv, B_ * M_, D_, D_, pks, bv);
}

// ================= elementwise / reduction kernels =================
__global__ void embed_kernel(const int* __restrict__ x, const float* __restrict__ emb,
                             const float* __restrict__ pos, float* __restrict__ h,
                             f16* __restrict__ ha)
{
    int row = blockIdx.x;
    int s   = row & (S_ - 1);
    int tok = __ldg(x + row);
    int c   = threadIdx.x * 4;
    float4 e = *reinterpret_cast<const float4*>(emb + (size_t)tok * D_ + c);
    float4 p = *reinterpret_cast<const float4*>(pos + (size_t)s * D_ + c);
    float4 o = make_float4(e.x + p.x, e.y + p.y, e.z + p.z, e.w + p.w);
    size_t ro = (size_t)row * D_ + c;
    *reinterpret_cast<float4*>(h + ro) = o;
    st_h2(ha, ro, o.x, o.y);
    st_h2(ha, ro + 2, o.z, o.w);
}

// G partials (128 d-cols per CTA, FFMA2) + fused pk column sums (dh==0 only)
__global__ void __launch_bounds__(256)
kvp_kernel(const float* __restrict__ pqk, int pstr, int poff,
           const f16* __restrict__ ha, float* __restrict__ part,
           float* __restrict__ pkp)
{
    const int dh = blockIdx.x;            // 0..3 (128-col block)
    const int b  = blockIdx.y;
    const int ch = blockIdx.z;            // 0..NCH-1
    __shared__ __align__(16) float spk[16][64];
    __shared__ __align__(16) float sv [16][128];
    const int tid = threadIdx.x, tx = tid & 15, ty = tid >> 4;
    unsigned long long acc[2][4][2];
#pragma unroll
    for (int dp = 0; dp < 2; dp++)
#pragma unroll
        for (int i = 0; i < 4; i++) { acc[dp][i][0] = 0ull; acc[dp][i][1] = 0ull; }
    float psum = 0.f;
    const int sbase = ch * (S_ / NCH);
    const int dbase = dh * 128;
    for (int s0 = 0; s0 < S_ / NCH; s0 += 16) {
        const int r = ty;
        size_t row = (size_t)b * S_ + sbase + s0 + r;
        *reinterpret_cast<float4*>(&spk[r][tx * 4]) =
            *reinterpret_cast<const float4*>(pqk + row * pstr + poff + tx * 4);
        const __half2* hp = reinterpret_cast<const __half2*>(ha + row * D_ + dbase + tx * 8);
#pragma unroll
        for (int q = 0; q < 4; q++) {
            float2 f = __half22float2(hp[q]);
            sv[r][tx * 8 + 2 * q]     = f.x;
            sv[r][tx * 8 + 2 * q + 1] = f.y;
        }
        __syncthreads();
        if (dh == 0 && tid < 64) {
#pragma unroll
            for (int rr = 0; rr < 16; rr++) psum += spk[rr][tid];
        }
#pragma unroll
        for (int kk = 0; kk < 16; kk++) {
            float4 am = *reinterpret_cast<float4*>(&spk[kk][ty * 4]);
            unsigned long long av[4] = {pack_dup(am.x), pack_dup(am.y),
                                        pack_dup(am.z), pack_dup(am.w)};
#pragma unroll
            for (int dp = 0; dp < 2; dp++) {
                unsigned long long b0 =
                    *reinterpret_cast<unsigned long long*>(&sv[kk][dp * 64 + tx * 4]);
                unsigned long long b1 =
                    *reinterpret_cast<unsigned long long*>(&sv[kk][dp * 64 + tx * 4 + 2]);
#pragma unroll
                for (int i = 0; i < 4; i++) {
                    ffma2(acc[dp][i][0], av[i], b0);
                    ffma2(acc[dp][i][1], av[i], b1);
                }
            }
        }
        __syncthreads();
    }
#pragma unroll
    for (int dp = 0; dp < 2; dp++)
#pragma unroll
        for (int i = 0; i < 4; i++) {
            size_t o = ((size_t)ch * B_ * M_ + (size_t)b * M_ + ty * 4 + i) * D_
                       + dbase + dp * 64 + tx * 4;
            *reinterpret_cast<float2*>(part + o)     = unpack2(acc[dp][i][0]);
            *reinterpret_cast<float2*>(part + o + 2) = unpack2(acc[dp][i][1]);
        }
    if (dh == 0 && tid < 64)
        pkp[(b * NCH + ch) * M_ + tid] = psum;
}

__global__ void pksum_red(const float* __restrict__ part, float* __restrict__ pks)
{
    int b = blockIdx.x, m = threadIdx.x;
    float s = 0.f;
#pragma unroll
    for (int c = 0; c < NCH; c++) s += part[(b * NCH + c) * M_ + m];
    pks[b * M_ + m] = s;
}

template <int RB, bool F16OUT>
__global__ void att_kernel(const float* __restrict__ pq, int pstr,
                           const float* __restrict__ kvm,
                           const float* __restrict__ pksum, float* __restrict__ att_f,
                           f16* __restrict__ att_h, int rows_per_batch)
{
    const int b  = blockIdx.y;
    const int r0 = blockIdx.x * RB;
    __shared__ float spq[RB][M_];
    __shared__ float spks[M_];
    __shared__ float sz[RB];
    const int tid = threadIdx.x;
    for (int i = tid; i < RB * M_; i += 256) {
        int r = i >> 6, m = i & 63;
        spq[r][m] = pq[((size_t)b * rows_per_batch + r0 + r) * pstr + m];
    }
    if (tid < M_) spks[tid] = pksum[b * M_ + tid];
    __syncthreads();
    if (tid < RB) {
        float z = 1e-6f;
#pragma unroll
        for (int m = 0; m < M_; m++) z = fmaf(spq[tid][m], spks[m], z);
        sz[tid] = z;
    }
    __syncthreads();
    const int d = 2 * tid;
    const float* kvb = kvm + (size_t)b * M_ * D_ + d;
    float2 acc[RB];
#pragma unroll
    for (int r = 0; r < RB; r++) acc[r] = make_float2(0.f, 0.f);
    for (int m = 0; m < M_; m += 4) {
        float2 kv0 = *reinterpret_cast<const float2*>(kvb + (size_t)(m + 0) * D_);
        float2 kv1 = *reinterpret_cast<const float2*>(kvb + (size_t)(m + 1) * D_);
        float2 kv2 = *reinterpret_cast<const float2*>(kvb + (size_t)(m + 2) * D_);
        float2 kv3 = *reinterpret_cast<const float2*>(kvb + (size_t)(m + 3) * D_);
#pragma unroll
        for (int r = 0; r < RB; r++) {
            acc[r].x = fmaf(spq[r][m],     kv0.x, acc[r].x);
            acc[r].y = fmaf(spq[r][m],     kv0.y, acc[r].y);
            acc[r].x = fmaf(spq[r][m + 1], kv1.x, acc[r].x);
            acc[r].y = fmaf(spq[r][m + 1], kv1.y, acc[r].y);
            acc[r].x = fmaf(spq[r][m + 2], kv2.x, acc[r].x);
            acc[r].y = fmaf(spq[r][m + 2], kv2.y, acc[r].y);
            acc[r].x = fmaf(spq[r][m + 3], kv3.x, acc[r].x);
            acc[r].y = fmaf(spq[r][m + 3], kv3.y, acc[r].y);
        }
    }
#pragma unroll
    for (int r = 0; r < RB; r++) {
        float inv = 1.0f / sz[r];
        float vx = acc[r].x * inv, vy = acc[r].y * inv;
        size_t o = ((size_t)b * rows_per_batch + r0 + r) * D_ + d;
        if (F16OUT) st_h2(att_h, o, vx, vy);
        else *reinterpret_cast<float2*>(att_f + o) = make_float2(vx, vy);
    }
}

// 2 rows per block, 256 threads
template <bool F16OUT>
__global__ void ln_kernel(const float* __restrict__ in, const float* __restrict__ g,
                          const float* __restrict__ bet, float* __restrict__ outf,
                          f16* __restrict__ outh)
{
    const int sub = threadIdx.x >> 7;
    const int row = blockIdx.x * 2 + sub;
    const int tid = threadIdx.x & 127;
    float4 v = *reinterpret_cast<const float4*>(in + (size_t)row * D_ + tid * 4);
    __shared__ float red[2][4];
    float s = v.x + v.y + v.z + v.w;
#pragma unroll
    for (int o = 16; o; o >>= 1) s += __shfl_xor_sync(0xffffffffu, s, o);
    if ((tid & 31) == 0) red[sub][tid >> 5] = s;
    __syncthreads();
    float mu = (red[sub][0] + red[sub][1] + red[sub][2] + red[sub][3]) * (1.f / 512.f);
    float dx = v.x - mu, dy = v.y - mu, dz = v.z - mu, dw = v.w - mu;
    float ss = dx * dx + dy * dy + dz * dz + dw * dw;
#pragma unroll
    for (int o = 16; o; o >>= 1) ss += __shfl_xor_sync(0xffffffffu, ss, o);
    __syncthreads();
    if ((tid & 31) == 0) red[sub][tid >> 5] = ss;
    __syncthreads();
    float var  = (red[sub][0] + red[sub][1] + red[sub][2] + red[sub][3]) * (1.f / 512.f);
    float rstd = rsqrtf(var + 1e-5f);
    float4 gg = *reinterpret_cast<const float4*>(g + tid * 4);
    float4 bb = *reinterpret_cast<const float4*>(bet + tid * 4);
    float o0 = dx * rstd * gg.x + bb.x, o1 = dy * rstd * gg.y + bb.y;
    float o2 = dz * rstd * gg.z + bb.z, o3 = dw * rstd * gg.w + bb.w;
    size_t ro = (size_t)row * D_ + tid * 4;
    if (F16OUT) {
        st_h2(outh, ro, o0, o1);
        st_h2(outh, ro + 2, o2, o3);
    } else {
        *reinterpret_cast<float4*>(outf + ro) = make_float4(o0, o1, o2, o3);
    }
}

__global__ void ln1_kernel(const float* __restrict__ in, const float* __restrict__ g,
                           const float* __restrict__ bet, float* __restrict__ outf)
{
    const int row = blockIdx.x;
    const int tid = threadIdx.x;
    float4 v = *reinterpret_cast<const float4*>(in + (size_t)row * D_ + tid * 4);
    __shared__ float red[4];
    float s = v.x + v.y + v.z + v.w;
#pragma unroll
    for (int o = 16; o; o >>= 1) s += __shfl_xor_sync(0xffffffffu, s, o);
    if ((tid & 31) == 0) red[tid >> 5] = s;
    __syncthreads();
    float mu = (red[0] + red[1] + red[2] + red[3]) * (1.f / 512.f);
    float dx = v.x - mu, dy = v.y - mu, dz = v.z - mu, dw = v.w - mu;
    float ss = dx * dx + dy * dy + dz * dz + dw * dw;
#pragma unroll
    for (int o = 16; o; o >>= 1) ss += __shfl_xor_sync(0xffffffffu, ss, o);
    __syncthreads();
    if ((tid & 31) == 0) red[tid >> 5] = ss;
    __syncthreads();
    float var  = (red[0] + red[1] + red[2] + red[3]) * (1.f / 512.f);
    float rstd = rsqrtf(var + 1e-5f);
    float4 gg = *reinterpret_cast<const float4*>(g + tid * 4);
    float4 bb = *reinterpret_cast<const float4*>(bet + tid * 4);
    *reinterpret_cast<float4*>(outf + (size_t)row * D_ + tid * 4) =
        make_float4(dx * rstd * gg.x + bb.x, dy * rstd * gg.y + bb.y,
                    dz * rstd * gg.z + bb.z, dw * rstd * gg.w + bb.w);
}

__global__ void gather0_kernel(const float* __restrict__ h, float* __restrict__ h0)
{
    int b = blockIdx.x;
    int c = threadIdx.x * 4;
    *reinterpret_cast<float4*>(h0 + (size_t)b * D_ + c) =
        *reinterpret_cast<const float4*>(h + (size_t)b * S_ * D_ + c);
}

__global__ void cls_kernel(const float* __restrict__ pooled, const float* __restrict__ Wc1,
                           const float* __restrict__ bc1, const float* __restrict__ Wc2,
                           const float* __restrict__ bc2, float* __restrict__ out)
{
    int b = blockIdx.x;
    int j = threadIdx.x;
    __shared__ float sp[D_];
    sp[j]       = pooled[(size_t)b * D_ + j];
    sp[j + 256] = pooled[(size_t)b * D_ + j + 256];
    __syncthreads();
    float acc = bc1[j];
    for (int d = 0; d < D_; d++) acc = fmaf(sp[d], Wc1[(size_t)d * 256 + j], acc);
    float hid = acc > 0.f ? acc : 0.f;
    float p0 = hid * Wc2[j * 2 + 0];
    float p1 = hid * Wc2[j * 2 + 1];
#pragma unroll
    for (int o = 16; o; o >>= 1) {
        p0 += __shfl_xor_sync(0xffffffffu, p0, o);
        p1 += __shfl_xor_sync(0xffffffffu, p1, o);
    }
    __shared__ float r0[8], r1[8];
    if ((j & 31) == 0) { r0[j >> 5] = p0; r1[j >> 5] = p1; }
    __syncthreads();
    if (j == 0) {
        float a0 = 0.f, a1 = 0.f;
#pragma unroll
        for (int w = 0; w < 8; w++) { a0 += r0[w]; a1 += r1[w]; }
        out[b * 2 + 0] = a0 + bc2[0];
        out[b * 2 + 1] = a1 + bc2[1];
    }
}

// ================= host =================
extern "C" void kernel_launch(void* const* d_in, const int* in_sizes, int n_in,
                              void* d_out, int out_size)
{
    const int*   x   = (const int*)  d_in[0];
    const float* emb = (const float*)d_in[1];
    const float* pos = (const float*)d_in[2];
    const float* Wq  = (const float*)d_in[3];
    const float* bq  = (const float*)d_in[4];
    const float* Wk  = (const float*)d_in[5];
    const float* bk  = (const float*)d_in[6];
    const float* Wv  = (const float*)d_in[7];
    const float* bv  = (const float*)d_in[8];
    const float* P   = (const float*)d_in[9];
    const float* Wo  = (const float*)d_in[10];
    const float* bo  = (const float*)d_in[11];
    const float* lng = (const float*)d_in[12];
    const float* lnb = (const float*)d_in[13];
    const float* W1  = (const float*)d_in[14];
    const float* b1  = (const float*)d_in[15];
    const float* W2  = (const float*)d_in[16];
    const float* b2  = (const float*)d_in[17];
    const float* Wc1 = (const float*)d_in[18];
    const float* bc1 = (const float*)d_in[19];
    const float* Wc2 = (const float*)d_in[20];
    const float* bc2 = (const float*)d_in[21];
    float* out = (float*)d_out;

    float *h_, *pqk_, *kvp_, *kv_, *pks_, *pkp_, *w_, *T_, *bPQK_;
    float *s0_, *s1_, *s2_, *s3_, *sff_;
    f16 *ha_, *at_, *ln_, *ff_, *PQKh_, *PQKl_;
    f16 *Woh,*Wol_,*W1h,*W1l_,*W2h,*W2l_;
    cudaGetSymbolAddress((void**)&h_,    g_h);
    cudaGetSymbolAddress((void**)&ha_,   g_ha);
    cudaGetSymbolAddress((void**)&pqk_,  g_pqk);
    cudaGetSymbolAddress((void**)&kvp_,  g_kvpart);
    cudaGetSymbolAddress((void**)&kv_,   g_kv);
    cudaGetSymbolAddress((void**)&pks_,  g_pks);
    cudaGetSymbolAddress((void**)&pkp_,  g_pkpart);
    cudaGetSymbolAddress((void**)&at_,   g_at);
    cudaGetSymbolAddress((void**)&w_,    g_w);
    cudaGetSymbolAddress((void**)&ln_,   g_ln);
    cudaGetSymbolAddress((void**)&ff_,   g_ff);
    cudaGetSymbolAddress((void**)&T_,    g_T);
    cudaGetSymbolAddress((void**)&bPQK_, g_bPQK);
    cudaGetSymbolAddress((void**)&PQKh_, g_PQKh);
    cudaGetSymbolAddress((void**)&PQKl_, g_PQKl);
    cudaGetSymbolAddress((void**)&s0_,   g_s0);
    cudaGetSymbolAddress((void**)&s1_,   g_s1);
    cudaGetSymbolAddress((void**)&s2_,   g_s2);
    cudaGetSymbolAddress((void**)&s3_,   g_s3);
    cudaGetSymbolAddress((void**)&sff_,  g_sff);
    cudaGetSymbolAddress((void**)&Woh, g_Woh); cudaGetSymbolAddress((void**)&Wol_, g_Wolo);
    cudaGetSymbolAddress((void**)&W1h, g_W1h); cudaGetSymbolAddress((void**)&W1l_, g_W1lo);
    cudaGetSymbolAddress((void**)&W2h, g_W2h); cudaGetSymbolAddress((void**)&W2l_, g_W2lo);

    dim3 t328(32, 8);
    foldP_kernel<<<dim3(D_ / 64, 2, L_), 256>>>(Wq, Wk, P, T_);
    wsplit2_kernel<<<dim3(2, 16, 2 * L_), t328>>>(T_, PQKh_, PQKl_);
    bfold_kernel<<<dim3(L_, 2), 64>>>(bq, bk, P, bPQK_);
    wsplit_kernel<<<dim3(16, 16, L_), t328>>>(Wo, D_, D_, Woh, Wol_);
    wsplit_kernel<<<dim3(64, 16, L_), t328>>>(W1, D_, H_, W1h, W1l_);
    wsplit_kernel<<<dim3(16, 64, L_), t328>>>(W2, H_, D_, W2h, W2l_);

    embed_kernel<<<NTOK, 128>>>(x, emb, pos, h_, ha_);

    for (int l = 0; l < 3; l++) {
        const size_t dd = (size_t)l * D_ * D_;
        const size_t hd = (size_t)l * H_ * D_, dh = (size_t)l * D_ * H_;
        tcg<128, ACT_ELU1, true, false, true, false>(ha_, PQKh_ + (size_t)l * 128 * D_,
            PQKl_ + (size_t)l * 128 * D_, bPQK_ + l * 128, nullptr, pqk_, nullptr,
            NTOK, 128, D_);
        kvp_kernel<<<dim3(4, B_, NCH), 256>>>(pqk_, 128, 64, ha_, kvp_, pkp_);
        pksum_red<<<B_, 64>>>(pkp_, pks_);
        gemm_outer(kvp_, Wv + dd, pks_, bv + (size_t)l * D_, kv_);
        att_kernel<16, true><<<dim3(S_ / 16, B_), 256>>>(pqk_, 128, kv_, pks_, nullptr, at_, S_);
        tcg<128, ACT_NONE, true, false, true, false>(at_, Woh + dd, Wol_ + dd, bo + l * D_,
            nullptr, w_, nullptr, NTOK, D_, D_);
        ln_kernel<true><<<NTOK / 2, 256>>>(w_, lng + l * D_, lnb + l * D_, nullptr, ln_);
        tcg<128, ACT_GELU, true, false, false, true>(ln_, W1h + hd, W1l_ + hd, b1 + l * H_,
            nullptr, nullptr, ff_, NTOK, H_, D_);
        tcg<128, ACT_NONE, true, true, true, true>(ff_, W2h + dh, W2l_ + dh, b2 + l * D_,
            h_, h_, ha_, NTOK, D_, H_);
    }

    { // layer 3: only position 0 survives
        const int l = 3;
        const size_t dd = (size_t)l * D_ * D_, md = (size_t)l * D_ * M_;
        gather0_kernel<<<B_, 128>>>(h_, s0_);
        tcg<64, ACT_ELU1, true, false, true, false>(ha_,
            PQKh_ + (size_t)l * 128 * D_ + (size_t)64 * D_,
            PQKl_ + (size_t)l * 128 * D_ + (size_t)64 * D_,
            bPQK_ + l * 128 + 64, nullptr, pqk_, nullptr, NTOK, 64, D_);
        kvp_kernel<<<dim3(4, B_, NCH), 256>>>(pqk_, 64, 0, ha_, kvp_, pkp_);
        pksum_red<<<B_, 64>>>(pkp_, pks_);
        gemm_outer(kvp_, Wv + dd, pks_, bv + (size_t)l * D_, kv_);

        gemm128<ACT_NONE, true, false>(s0_, Wq + dd, bq + l * D_, nullptr, s1_, B_, D_, D_);
        gemm64n<ACT_ELU1>(s1_, P + md, s2_, B_, D_);
        att_kernel<1, false><<<dim3(1, B_), 256>>>(s2_, 64, kv_, pks_, s3_, nullptr, 1);
        gemm128<ACT_NONE, true, false>(s3_, Wo + dd, bo + l * D_, nullptr, s1_, B_, D_, D_);
        ln1_kernel<<<B_, 128>>>(s1_, lng + l * D_, lnb + l * D_, s3_);
        gemm128<ACT_GELU, true, false>(s3_, W1 + (size_t)l * D_ * H_, b1 + l * H_, nullptr, sff_, B_, H_, D_);
        gemm128<ACT_NONE, true, true >(sff_, W2 + (size_t)l * H_ * D_, b2 + l * D_, s0_, s1_, B_, D_, H_);
    }

    cls_kernel<<<B_, 256>>>(s1_, Wc1, bc1, Wc2, bc2, out);
}

// round 17
// speedup vs baseline: 1.0865x; 1.0865x over previous
#include <cuda_runtime.h>
#include <cuda_fp16.h>
#include <math.h>
#include <stdint.h>

#define DEV_INLINE __device__ __forceinline__

#define B_    16
#define S_    2048
#define D_    512
#define H_    2048
#define L_    4
#define M_    64
#define NTOK  (B_ * S_)
#define NCH   4                               // S-split chunks for kv pipeline

typedef __half  f16;

// ---------------- scratch ----------------
__device__ float g_h  [NTOK * D_];
__device__ f16   g_ha [NTOK * D_];
__device__ float g_pqk[NTOK * 128];                // stride 128: pq 0:64, pk 64:128 (layer3: stride 64)
__device__ float g_kvpart[NCH * B_ * M_ * D_];     // S-split partials of G
__device__ float g_kv [B_ * M_ * D_];
__device__ float g_pks[B_ * M_];
__device__ float g_pkpart[B_ * NCH * M_];
__device__ f16   g_at [NTOK * D_];
__device__ float g_w  [NTOK * D_];
__device__ f16   g_ln [NTOK * D_];
__device__ f16   g_ff [NTOK * H_];
__device__ float g_s0 [B_ * D_], g_s1 [B_ * D_], g_s2 [B_ * M_], g_s3 [B_ * D_], g_sff[B_ * H_];
__device__ float g_T   [L_ * 2 * D_ * M_];
__device__ f16   g_PQKh[L_ * 128 * D_], g_PQKl[L_ * 128 * D_];
__device__ float g_bPQK[L_ * 128];
__device__ f16 g_Woh[L_*D_*D_], g_Wolo[L_*D_*D_];
__device__ f16 g_W1h[L_*H_*D_], g_W1lo[L_*H_*D_];
__device__ f16 g_W2h[L_*D_*H_], g_W2lo[L_*D_*H_];

// ---------------- helpers ----------------
DEV_INLINE uint32_t smem_u32(const void* p) {
    uint32_t a;
    asm("{ .reg .u64 t; cvta.to.shared.u64 t, %1; cvt.u32.u64 %0, t; }" : "=r"(a) : "l"(p));
    return a;
}
DEV_INLINE void cp16(uint32_t dst, const void* src) {
    asm volatile("cp.async.cg.shared.global [%0], [%1], 16;"
                 :: "r"(dst), "l"(__cvta_generic_to_global(src)));
}
DEV_INLINE void cp_commit() { asm volatile("cp.async.commit_group;"); }
template<int N> DEV_INLINE void cp_wait() {
    asm volatile("cp.async.wait_group %0;" :: "n"(N) : "memory");
}
DEV_INLINE void ldm_x4(uint32_t& r0, uint32_t& r1, uint32_t& r2, uint32_t& r3, uint32_t addr) {
    asm volatile("ldmatrix.sync.aligned.m8n8.x4.shared.b16 {%0,%1,%2,%3}, [%4];"
                 : "=r"(r0), "=r"(r1), "=r"(r2), "=r"(r3) : "r"(addr));
}
DEV_INLINE void mma16816(float* d, const uint32_t* a, const uint32_t* b) {
    asm volatile("mma.sync.aligned.m16n8k16.row.col.f32.f16.f16.f32 "
                 "{%0,%1,%2,%3}, {%4,%5,%6,%7}, {%8,%9}, {%0,%1,%2,%3};"
                 : "+f"(d[0]), "+f"(d[1]), "+f"(d[2]), "+f"(d[3])
                 : "r"(a[0]), "r"(a[1]), "r"(a[2]), "r"(a[3]), "r"(b[0]), "r"(b[1]));
}
DEV_INLINE void split_f16(float v, f16& h, f16& l) {
    h = __float2half_rn(v);
    l = __float2half_rn(v - __half2float(h));
}
DEV_INLINE void st_h2(f16* C, size_t o, float x, float y) {
    *reinterpret_cast<__half2*>(C + o) = __floats2half2_rn(x, y);
}
DEV_INLINE unsigned long long pack_dup(float a) {
    unsigned long long r;
    asm("mov.b64 %0, {%1, %2};" : "=l"(r) : "f"(a), "f"(a));
    return r;
}
DEV_INLINE void ffma2(unsigned long long& d, unsigned long long a, unsigned long long b) {
    asm("fma.rn.f32x2 %0, %1, %2, %0;" : "+l"(d) : "l"(a), "l"(b));
}
DEV_INLINE float2 unpack2(unsigned long long v) {
    float2 f;
    asm("mov.b64 {%0, %1}, %2;" : "=f"(f.x), "=f"(f.y) : "l"(v));
    return f;
}

enum { ACT_NONE = 0, ACT_ELU1 = 1, ACT_GELU = 2 };

// ========== fp16 2-MMA split GEMM, 2-stage cp.async, single-sync mainloop ==========
template<int BN, int ACT, bool HAS_BIAS, bool ADD_RES, bool OUT_F32, bool OUT_F16>
__global__ void __launch_bounds__(256, 2)
mma_gemm_kernel(const f16* __restrict__ A, const f16* __restrict__ Bh,
                const f16* __restrict__ Bl, const float* __restrict__ bias,
                const float* __restrict__ res,
                float* __restrict__ Cf, f16* __restrict__ Ch,
                int M, int N, int K)
{
    constexpr int SA    = 72;
    constexpr int ABYT  = 128 * SA * 2;
    constexpr int BBYT  = BN * SA * 2;
    constexpr int STAGE = ABYT + 2 * BBYT;
    constexpr int WN = BN / 4, NT = WN / 8, NG = WN / 16;

    extern __shared__ __align__(16) char smem[];
    const int tid  = threadIdx.x;
    const int wid  = tid >> 5;
    const int lane = tid & 31;
    const int bm   = blockIdx.y * 128;
    const int bn   = blockIdx.x * BN;
    const int wm   = (wid >> 2) * 64;
    const int wn   = (wid & 3) * WN;

    float acc[4][NT][4];
#pragma unroll
    for (int i = 0; i < 4; i++)
#pragma unroll
        for (int j = 0; j < NT; j++)
#pragma unroll
            for (int q = 0; q < 4; q++) acc[i][j][q] = 0.f;

    const uint32_t smb = smem_u32(smem);
    auto load_stage = [&](int c, int s) {
        const size_t ko = (size_t)c * 64;
        const uint32_t base = smb + (uint32_t)s * STAGE;
#pragma unroll
        for (int i = 0; i < 4; i++) {
            int idx = tid + i * 256;
            int r = idx >> 3, cs = idx & 7;
            cp16(base + (uint32_t)(r * SA + cs * 8) * 2,
                 A + (size_t)(bm + r) * K + ko + cs * 8);
        }
#pragma unroll
        for (int i = 0; i < BN * 8 / 256; i++) {
            int idx = tid + i * 256;
            int r = idx >> 3, cs = idx & 7;
            uint32_t off = (uint32_t)(r * SA + cs * 8) * 2;
            const size_t go = (size_t)(bn + r) * K + ko + cs * 8;
            cp16(base + ABYT + off,        Bh + go);
            cp16(base + ABYT + BBYT + off, Bl + go);
        }
        cp_commit();
    };

    const int C_ = K >> 6;
    load_stage(0, 0);

    const int arow  = (lane & 15);
    const int acol8 = (lane >> 4) * 8;
    const int brow  = (lane & 7) + ((lane >> 4) & 1) * 8;
    const int bcol8 = ((lane >> 3) & 1) * 8;

    for (int c = 0; c < C_; c++) {
        cp_wait<0>();          // stage c resident
        __syncthreads();       // publishes stage c AND retires all reads of slot (c+1)&1
        if (c + 1 < C_) load_stage(c + 1, (c + 1) & 1);

        const uint32_t a_base  = smb + (uint32_t)(c & 1) * STAGE;
        const uint32_t bh_base = a_base + ABYT;
        const uint32_t bl_base = bh_base + BBYT;

#pragma unroll
        for (int kk = 0; kk < 4; kk++) {
            uint32_t ar[4][4];
#pragma unroll
            for (int mi = 0; mi < 4; mi++) {
                uint32_t off = (uint32_t)((wm + mi * 16 + arow) * SA + kk * 16 + acol8) * 2;
                ldm_x4(ar[mi][0], ar[mi][1], ar[mi][2], ar[mi][3], a_base + off);
            }
            uint32_t bh[NT][2], bl[NT][2];
#pragma unroll
            for (int g = 0; g < NG; g++) {
                uint32_t off = (uint32_t)((wn + g * 16 + brow) * SA + kk * 16 + bcol8) * 2;
                uint32_t r0, r1, r2, r3;
                ldm_x4(r0, r1, r2, r3, bh_base + off);
                bh[2*g][0] = r0; bh[2*g][1] = r1; bh[2*g+1][0] = r2; bh[2*g+1][1] = r3;
                ldm_x4(r0, r1, r2, r3, bl_base + off);
                bl[2*g][0] = r0; bl[2*g][1] = r1; bl[2*g+1][0] = r2; bl[2*g+1][1] = r3;
            }
#pragma unroll
            for (int mi = 0; mi < 4; mi++)
#pragma unroll
                for (int nt = 0; nt < NT; nt++) {
                    mma16816(acc[mi][nt], ar[mi], bh[nt]);
                    mma16816(acc[mi][nt], ar[mi], bl[nt]);
                }
        }
    }

    const int rbase = bm + wm + (lane >> 2);
    const int cbase = bn + wn + (lane & 3) * 2;
#pragma unroll
    for (int mi = 0; mi < 4; mi++) {
#pragma unroll
        for (int nt = 0; nt < NT; nt++) {
            const int col = cbase + nt * 8;
            float bx = 0.f, by = 0.f;
            if (HAS_BIAS) { bx = __ldg(bias + col); by = __ldg(bias + col + 1); }
#pragma unroll
            for (int half = 0; half < 2; half++) {
                const int row = rbase + mi * 16 + half * 8;
                float vx = acc[mi][nt][half * 2 + 0] + bx;
                float vy = acc[mi][nt][half * 2 + 1] + by;
                if (ACT == ACT_ELU1) {
                    vx = (vx > 0.f) ? vx + 1.f : expf(vx);
                    vy = (vy > 0.f) ? vy + 1.f : expf(vy);
                } else if (ACT == ACT_GELU) {
                    vx = 0.5f * vx * (1.f + erff(vx * 0.70710678118654752f));
                    vy = 0.5f * vy * (1.f + erff(vy * 0.70710678118654752f));
                }
                const size_t ro = (size_t)row * N + col;
                if (ADD_RES) {
                    float2 rr = *reinterpret_cast<const float2*>(res + ro);
                    vx += rr.x; vy += rr.y;
                }
                if (OUT_F32)
                    *reinterpret_cast<float2*>(Cf + ro) = make_float2(vx, vy);
                if (OUT_F16)
                    st_h2(Ch, ro, vx, vy);
            }
        }
    }
}

template<int BN, int ACT, bool HB, bool AR, bool OF, bool OH>
static void tcg(const f16* A, const f16* Bh, const f16* Bl, const float* bias,
                const float* res, float* Cf, f16* Ch, int M, int N, int K)
{
    constexpr int STAGE = (128 * 72 * 2) + 2 * (BN * 72 * 2);
    size_t sm = 2 * (size_t)STAGE;
    auto k = mma_gemm_kernel<BN, ACT, HB, AR, OF, OH>;
    cudaFuncSetAttribute(k, cudaFuncAttributeMaxDynamicSharedMemorySize, (int)sm);
    k<<<dim3(N / BN, M / 128), 256, sm>>>(A, Bh, Bl, bias, res, Cf, Ch, M, N, K);
}

// ============ weight transpose+split ============
__global__ void wsplit_kernel(const float* __restrict__ W, int K, int N,
                              f16* __restrict__ Wh, f16* __restrict__ Wl)
{
    __shared__ float tile[32][33];
    const int l = blockIdx.z;
    const float* Ws = W + (size_t)l * K * N;
    f16* Whd = Wh + (size_t)l * N * K;
    f16* Wld = Wl + (size_t)l * N * K;
    const int n0 = blockIdx.x * 32, k0 = blockIdx.y * 32;
    const int tx = threadIdx.x, ty = threadIdx.y;
#pragma unroll
    for (int i = 0; i < 4; i++)
        tile[ty + i * 8][tx] = Ws[(size_t)(k0 + ty + i * 8) * N + n0 + tx];
    __syncthreads();
#pragma unroll
    for (int i = 0; i < 4; i++) {
        float v = tile[tx][ty + i * 8];
        f16 h, lo; split_f16(v, h, lo);
        size_t o = (size_t)(n0 + ty + i * 8) * K + k0 + tx;
        Whd[o] = h; Wld[o] = lo;
    }
}

__global__ void wsplit2_kernel(const float* __restrict__ T,
                               f16* __restrict__ Wh, f16* __restrict__ Wl)
{
    __shared__ float tile[32][33];
    const int z = blockIdx.z;
    const float* Ws = T + (size_t)z * D_ * M_;
    const size_t ob = (size_t)(z >> 1) * (128 * D_) + (size_t)(z & 1) * 64 * D_;
    f16* Whd = Wh + ob;
    f16* Wld = Wl + ob;
    const int n0 = blockIdx.x * 32, k0 = blockIdx.y * 32;
    const int tx = threadIdx.x, ty = threadIdx.y;
#pragma unroll
    for (int i = 0; i < 4; i++)
        tile[ty + i * 8][tx] = Ws[(size_t)(k0 + ty + i * 8) * M_ + n0 + tx];
    __syncthreads();
#pragma unroll
    for (int i = 0; i < 4; i++) {
        float v = tile[tx][ty + i * 8];
        f16 h, lo; split_f16(v, h, lo);
        size_t o = (size_t)(n0 + ty + i * 8) * D_ + k0 + tx;
        Whd[o] = h; Wld[o] = lo;
    }
}

// ============ fold Wq@P / Wk@P ============
__global__ void foldP_kernel(const float* __restrict__ Wq, const float* __restrict__ Wk,
                             const float* __restrict__ P, float* __restrict__ T)
{
    const int dblk = blockIdx.x;
    const int sel  = blockIdx.y;
    const int l    = blockIdx.z;
    const float* W  = (sel ? Wk : Wq) + (size_t)l * D_ * D_;
    const float* Pl = P + (size_t)l * D_ * M_;
    __shared__ float sW[64][65];
    __shared__ float sP[64][64];
    const int tid = threadIdx.x;
    const int tr = tid >> 4, tc = tid & 15;
    float acc[4][4] = {};
    for (int e0 = 0; e0 < D_; e0 += 64) {
#pragma unroll
        for (int i = 0; i < 16; i++) {
            int idx = tid + i * 256;
            int r = idx >> 6, c = idx & 63;
            sW[r][c] = W[(size_t)(dblk * 64 + r) * D_ + e0 + c];
            sP[r][c] = Pl[(size_t)(e0 + r) * M_ + c];
        }
        __syncthreads();
#pragma unroll 16
        for (int e = 0; e < 64; e++) {
            float pv[4];
#pragma unroll
            for (int j = 0; j < 4; j++) pv[j] = sP[e][tc * 4 + j];
#pragma unroll
            for (int i = 0; i < 4; i++) {
                float wv = sW[tr * 4 + i][e];
#pragma unroll
                for (int j = 0; j < 4; j++) acc[i][j] = fmaf(wv, pv[j], acc[i][j]);
            }
        }
        __syncthreads();
    }
    float* Tout = T + (size_t)(l * 2 + sel) * D_ * M_;
#pragma unroll
    for (int i = 0; i < 4; i++)
#pragma unroll
        for (int j = 0; j < 4; j++)
            Tout[(size_t)(dblk * 64 + tr * 4 + i) * M_ + tc * 4 + j] = acc[i][j];
}

__global__ void bfold_kernel(const float* __restrict__ bq, const float* __restrict__ bk,
                             const float* __restrict__ P, float* __restrict__ bPQK)
{
    const int l = blockIdx.x, sel = blockIdx.y, m = threadIdx.x;
    const float* b  = (sel ? bk : bq) + (size_t)l * D_;
    const float* Pl = P + (size_t)l * D_ * M_;
    float s = 0.f;
    for (int d = 0; d < D_; d++) s = fmaf(b[d], Pl[(size_t)d * M_ + m], s);
    bPQK[l * 128 + sel * 64 + m] = s;
}

// ================= fp32 FFMA2 SGEMM (+outer epilogue, +NCH-way A sum) =================
template <int BM, int BN, int BK, int TM, int TN, int ACT, bool HAS_BIAS, bool ADD_RES,
          bool ADD_OUTER, bool A_SUM>
__global__ void __launch_bounds__((BM / TM) * (BN / TN))
gemm_kernel(const float* __restrict__ A, const float* __restrict__ Bw,
            const float* __restrict__ bias, const float* __restrict__ res,
            float* __restrict__ C, int M, int N, int K,
            const float* __restrict__ rowscale, const float* __restrict__ colvec)
{
    constexpr int THREADS = (BM / TM) * (BN / TN);
    __shared__ __align__(16) float As[BK][BM];
    __shared__ __align__(16) float Bs[BK][BN];
    const int bm = blockIdx.y * BM, bn = blockIdx.x * BN, tid = threadIdx.x;
    constexpr int TCOLS = BN / TN;
    const int tc = tid % TCOLS, tr = tid / TCOLS;
    unsigned long long acc[TM][TN / 2];
#pragma unroll
    for (int i = 0; i < TM; i++)
#pragma unroll
        for (int j = 0; j < TN / 2; j++) acc[i][j] = 0ull;
    for (int k0 = 0; k0 < K; k0 += BK) {
        for (int i = tid; i < BM * BK / 4; i += THREADS) {
            int r = i / (BK / 4), kc = (i % (BK / 4)) * 4, gr = bm + r;
            float4 v4 = make_float4(0.f, 0.f, 0.f, 0.f);
            if (gr < M) {
                if (A_SUM) {
#pragma unroll
                    for (int ch = 0; ch < NCH; ch++) {
                        float4 p = *reinterpret_cast<const float4*>(
                            A + (size_t)ch * (B_ * M_ * D_) + (size_t)gr * K + k0 + kc);
                        v4.x += p.x; v4.y += p.y; v4.z += p.z; v4.w += p.w;
                    }
                } else {
                    v4 = *reinterpret_cast<const float4*>(A + (size_t)gr * K + k0 + kc);
                }
            }
            As[kc][r] = v4.x; As[kc+1][r] = v4.y; As[kc+2][r] = v4.z; As[kc+3][r] = v4.w;
        }
        for (int i = tid; i < BK * BN / 4; i += THREADS) {
            int r = i / (BN / 4), c = (i % (BN / 4)) * 4;
            *reinterpret_cast<float4*>(&Bs[r][c]) =
                *reinterpret_cast<const float4*>(Bw + (size_t)(k0 + r) * N + bn + c);
        }
        __syncthreads();
#pragma unroll
        for (int kk = 0; kk < BK; kk++) {
            unsigned long long ar[TM], br[TN / 2];
#pragma unroll
            for (int i = 0; i < TM; i++) ar[i] = pack_dup(As[kk][tr * TM + i]);
#pragma unroll
            for (int j = 0; j < TN / 2; j++)
                br[j] = *reinterpret_cast<const unsigned long long*>(&Bs[kk][tc * TN + 2 * j]);
#pragma unroll
            for (int i = 0; i < TM; i++)
#pragma unroll
                for (int j = 0; j < TN / 2; j++) ffma2(acc[i][j], ar[i], br[j]);
        }
        __syncthreads();
    }
#pragma unroll
    for (int i = 0; i < TM; i++) {
        int gr = bm + tr * TM + i;
        if (gr >= M) continue;
        float rs = 0.f;
        if (ADD_OUTER) rs = __ldg(rowscale + gr);
#pragma unroll
        for (int j = 0; j < TN / 2; j++) {
            int gc = bn + tc * TN + 2 * j;
            float2 v = unpack2(acc[i][j]);
            if (HAS_BIAS) { v.x += bias[gc]; v.y += bias[gc + 1]; }
            if (ADD_OUTER) {
                v.x += rs * __ldg(colvec + gc);
                v.y += rs * __ldg(colvec + gc + 1);
            }
            if (ACT == ACT_ELU1) {
                v.x = (v.x > 0.f) ? v.x + 1.f : expf(v.x);
                v.y = (v.y > 0.f) ? v.y + 1.f : expf(v.y);
            } else if (ACT == ACT_GELU) {
                v.x = 0.5f * v.x * (1.f + erff(v.x * 0.70710678118654752f));
                v.y = 0.5f * v.y * (1.f + erff(v.y * 0.70710678118654752f));
            }
            if (ADD_RES) {
                float2 rv = *reinterpret_cast<const float2*>(res + (size_t)gr * N + gc);
                v.x += rv.x; v.y += rv.y;
            }
            *reinterpret_cast<float2*>(C + (size_t)gr * N + gc) = v;
        }
    }
}

template <int ACT, bool HB, bool AR>
static void gemm128(const float* A, const float* Bw, const float* bias, const float* res,
                    float* C, int M, int N, int K)
{
    dim3 grid(N / 128, (M + 127) / 128);
    gemm_kernel<128, 128, 16, 8, 8, ACT, HB, AR, false, false><<<grid, 256>>>(
        A, Bw, bias, res, C, M, N, K, nullptr, nullptr);
}
template <int ACT>
static void gemm64n(const float* A, const float* Bw, float* C, int M, int K)
{
    dim3 grid(1, (M + 127) / 128);
    gemm_kernel<128, 64, 16, 8, 8, ACT, false, false, false, false><<<grid, 128>>>(
        A, Bw, nullptr, nullptr, C, M, 64, K, nullptr, nullptr);
}
static void gemm_outer(const float* part, const float* Wv, const float* pks, const float* bv,
                       float* kv)
{
    dim3 grid(D_ / 64, B_ * M_ / 64);
    gemm_kernel<64, 64, 16, 4, 4, ACT_NONE, false, false, true, true><<<grid, 256>>>(
        part, Wv, nullptr, nullptr, kv, B_ * M_, D_, D_, pks, bv);
}

// ================= elementwise / reduction kernels =================
__global__ void embed_kernel(const int* __restrict__ x, const float* __restrict__ emb,
                             const float* __restrict__ pos, float* __restrict__ h,
                             f16* __restrict__ ha)
{
    int row = blockIdx.x;
    int s   = row & (S_ - 1);
    int tok = __ldg(x + row);
    int c   = threadIdx.x * 4;
    float4 e = *reinterpret_cast<const float4*>(emb + (size_t)tok * D_ + c);
    float4 p = *reinterpret_cast<const float4*>(pos + (size_t)s * D_ + c);
    float4 o = make_float4(e.x + p.x, e.y + p.y, e.z + p.z, e.w + p.w);
    size_t ro = (size_t)row * D_ + c;
    *reinterpret_cast<float4*>(h + ro) = o;
    st_h2(ha, ro, o.x, o.y);
    st_h2(ha, ro + 2, o.z, o.w);
}

// G partials (128 d-cols per CTA, FFMA2) + fused pk column sums (dh==0 only)
__global__ void __launch_bounds__(256)
kvp_kernel(const float* __restrict__ pqk, int pstr, int poff,
           const f16* __restrict__ ha, float* __restrict__ part,
           float* __restrict__ pkp)
{
    const int dh = blockIdx.x;            // 0..3 (128-col block)
    const int b  = blockIdx.y;
    const int ch = blockIdx.z;            // 0..NCH-1
    __shared__ __align__(16) float spk[16][64];
    __shared__ __align__(16) float sv [16][128];
    const int tid = threadIdx.x, tx = tid & 15, ty = tid >> 4;
    unsigned long long acc[2][4][2];
#pragma unroll
    for (int dp = 0; dp < 2; dp++)
#pragma unroll
        for (int i = 0; i < 4; i++) { acc[dp][i][0] = 0ull; acc[dp][i][1] = 0ull; }
    float psum = 0.f;
    const int sbase = ch * (S_ / NCH);
    const int dbase = dh * 128;
    for (int s0 = 0; s0 < S_ / NCH; s0 += 16) {
        const int r = ty;
        size_t row = (size_t)b * S_ + sbase + s0 + r;
        *reinterpret_cast<float4*>(&spk[r][tx * 4]) =
            *reinterpret_cast<const float4*>(pqk + row * pstr + poff + tx * 4);
        const __half2* hp = reinterpret_cast<const __half2*>(ha + row * D_ + dbase + tx * 8);
#pragma unroll
        for (int q = 0; q < 4; q++) {
            float2 f = __half22float2(hp[q]);
            sv[r][tx * 8 + 2 * q]     = f.x;
            sv[r][tx * 8 + 2 * q + 1] = f.y;
        }
        __syncthreads();
        if (dh == 0 && tid < 64) {
#pragma unroll
            for (int rr = 0; rr < 16; rr++) psum += spk[rr][tid];
        }
#pragma unroll
        for (int kk = 0; kk < 16; kk++) {
            float4 am = *reinterpret_cast<float4*>(&spk[kk][ty * 4]);
            unsigned long long av[4] = {pack_dup(am.x), pack_dup(am.y),
                                        pack_dup(am.z), pack_dup(am.w)};
#pragma unroll
            for (int dp = 0; dp < 2; dp++) {
                unsigned long long b0 =
                    *reinterpret_cast<unsigned long long*>(&sv[kk][dp * 64 + tx * 4]);
                unsigned long long b1 =
                    *reinterpret_cast<unsigned long long*>(&sv[kk][dp * 64 + tx * 4 + 2]);
#pragma unroll
                for (int i = 0; i < 4; i++) {
                    ffma2(acc[dp][i][0], av[i], b0);
                    ffma2(acc[dp][i][1], av[i], b1);
                }
            }
        }
        __syncthreads();
    }
#pragma unroll
    for (int dp = 0; dp < 2; dp++)
#pragma unroll
        for (int i = 0; i < 4; i++) {
            size_t o = ((size_t)ch * B_ * M_ + (size_t)b * M_ + ty * 4 + i) * D_
                       + dbase + dp * 64 + tx * 4;
            *reinterpret_cast<float2*>(part + o)     = unpack2(acc[dp][i][0]);
            *reinterpret_cast<float2*>(part + o + 2) = unpack2(acc[dp][i][1]);
        }
    if (dh == 0 && tid < 64)
        pkp[(b * NCH + ch) * M_ + tid] = psum;
}

__global__ void pksum_red(const float* __restrict__ part, float* __restrict__ pks)
{
    int b = blockIdx.x, m = threadIdx.x;
    float s = 0.f;
#pragma unroll
    for (int c = 0; c < NCH; c++) s += part[(b * NCH + c) * M_ + m];
    pks[b * M_ + m] = s;
}

template <int RB, bool F16OUT>
__global__ void att_kernel(const float* __restrict__ pq, int pstr,
                           const float* __restrict__ kvm,
                           const float* __restrict__ pksum, float* __restrict__ att_f,
                           f16* __restrict__ att_h, int rows_per_batch)
{
    const int b  = blockIdx.y;
    const int r0 = blockIdx.x * RB;
    __shared__ float spq[RB][M_];
    __shared__ float spks[M_];
    __shared__ float sz[RB];
    const int tid = threadIdx.x;
    for (int i = tid; i < RB * M_; i += 256) {
        int r = i >> 6, m = i & 63;
        spq[r][m] = pq[((size_t)b * rows_per_batch + r0 + r) * pstr + m];
    }
    if (tid < M_) spks[tid] = pksum[b * M_ + tid];
    __syncthreads();
    if (tid < RB) {
        float z = 1e-6f;
#pragma unroll
        for (int m = 0; m < M_; m++) z = fmaf(spq[tid][m], spks[m], z);
        sz[tid] = z;
    }
    __syncthreads();
    const int d = 2 * tid;
    const float* kvb = kvm + (size_t)b * M_ * D_ + d;
    float2 acc[RB];
#pragma unroll
    for (int r = 0; r < RB; r++) acc[r] = make_float2(0.f, 0.f);
    for (int m = 0; m < M_; m += 8) {
        float2 kv0 = *reinterpret_cast<const float2*>(kvb + (size_t)(m + 0) * D_);
        float2 kv1 = *reinterpret_cast<const float2*>(kvb + (size_t)(m + 1) * D_);
        float2 kv2 = *reinterpret_cast<const float2*>(kvb + (size_t)(m + 2) * D_);
        float2 kv3 = *reinterpret_cast<const float2*>(kvb + (size_t)(m + 3) * D_);
        float2 kv4 = *reinterpret_cast<const float2*>(kvb + (size_t)(m + 4) * D_);
        float2 kv5 = *reinterpret_cast<const float2*>(kvb + (size_t)(m + 5) * D_);
        float2 kv6 = *reinterpret_cast<const float2*>(kvb + (size_t)(m + 6) * D_);
        float2 kv7 = *reinterpret_cast<const float2*>(kvb + (size_t)(m + 7) * D_);
#pragma unroll
        for (int r = 0; r < RB; r++) {
            acc[r].x = fmaf(spq[r][m],     kv0.x, acc[r].x);
            acc[r].y = fmaf(spq[r][m],     kv0.y, acc[r].y);
            acc[r].x = fmaf(spq[r][m + 1], kv1.x, acc[r].x);
            acc[r].y = fmaf(spq[r][m + 1], kv1.y, acc[r].y);
            acc[r].x = fmaf(spq[r][m + 2], kv2.x, acc[r].x);
            acc[r].y = fmaf(spq[r][m + 2], kv2.y, acc[r].y);
            acc[r].x = fmaf(spq[r][m + 3], kv3.x, acc[r].x);
            acc[r].y = fmaf(spq[r][m + 3], kv3.y, acc[r].y);
            acc[r].x = fmaf(spq[r][m + 4], kv4.x, acc[r].x);
            acc[r].y = fmaf(spq[r][m + 4], kv4.y, acc[r].y);
            acc[r].x = fmaf(spq[r][m + 5], kv5.x, acc[r].x);
            acc[r].y = fmaf(spq[r][m + 5], kv5.y, acc[r].y);
            acc[r].x = fmaf(spq[r][m + 6], kv6.x, acc[r].x);
            acc[r].y = fmaf(spq[r][m + 6], kv6.y, acc[r].y);
            acc[r].x = fmaf(spq[r][m + 7], kv7.x, acc[r].x);
            acc[r].y = fmaf(spq[r][m + 7], kv7.y, acc[r].y);
        }
    }
#pragma unroll
    for (int r = 0; r < RB; r++) {
        float inv = 1.0f / sz[r];
        float vx = acc[r].x * inv, vy = acc[r].y * inv;
        size_t o = ((size_t)b * rows_per_batch + r0 + r) * D_ + d;
        if (F16OUT) st_h2(att_h, o, vx, vy);
        else *reinterpret_cast<float2*>(att_f + o) = make_float2(vx, vy);
    }
}

// 2 rows per block, 256 threads
template <bool F16OUT>
__global__ void ln_kernel(const float* __restrict__ in, const float* __restrict__ g,
                          const float* __restrict__ bet, float* __restrict__ outf,
                          f16* __restrict__ outh)
{
    const int sub = threadIdx.x >> 7;
    const int row = blockIdx.x * 2 + sub;
    const int tid = threadIdx.x & 127;
    float4 v = *reinterpret_cast<const float4*>(in + (size_t)row * D_ + tid * 4);
    __shared__ float red[2][4];
    float s = v.x + v.y + v.z + v.w;
#pragma unroll
    for (int o = 16; o; o >>= 1) s += __shfl_xor_sync(0xffffffffu, s, o);
    if ((tid & 31) == 0) red[sub][tid >> 5] = s;
    __syncthreads();
    float mu = (red[sub][0] + red[sub][1] + red[sub][2] + red[sub][3]) * (1.f / 512.f);
    float dx = v.x - mu, dy = v.y - mu, dz = v.z - mu, dw = v.w - mu;
    float ss = dx * dx + dy * dy + dz * dz + dw * dw;
#pragma unroll
    for (int o = 16; o; o >>= 1) ss += __shfl_xor_sync(0xffffffffu, ss, o);
    __syncthreads();
    if ((tid & 31) == 0) red[sub][tid >> 5] = ss;
    __syncthreads();
    float var  = (red[sub][0] + red[sub][1] + red[sub][2] + red[sub][3]) * (1.f / 512.f);
    float rstd = rsqrtf(var + 1e-5f);
    float4 gg = *reinterpret_cast<const float4*>(g + tid * 4);
    float4 bb = *reinterpret_cast<const float4*>(bet + tid * 4);
    float o0 = dx * rstd * gg.x + bb.x, o1 = dy * rstd * gg.y + bb.y;
    float o2 = dz * rstd * gg.z + bb.z, o3 = dw * rstd * gg.w + bb.w;
    size_t ro = (size_t)row * D_ + tid * 4;
    if (F16OUT) {
        st_h2(outh, ro, o0, o1);
        st_h2(outh, ro + 2, o2, o3);
    } else {
        *reinterpret_cast<float4*>(outf + ro) = make_float4(o0, o1, o2, o3);
    }
}

__global__ void ln1_kernel(const float* __restrict__ in, const float* __restrict__ g,
                           const float* __restrict__ bet, float* __restrict__ outf)
{
    const int row = blockIdx.x;
    const int tid = threadIdx.x;
    float4 v = *reinterpret_cast<const float4*>(in + (size_t)row * D_ + tid * 4);
    __shared__ float red[4];
    float s = v.x + v.y + v.z + v.w;
#pragma unroll
    for (int o = 16; o; o >>= 1) s += __shfl_xor_sync(0xffffffffu, s, o);
    if ((tid & 31) == 0) red[tid >> 5] = s;
    __syncthreads();
    float mu = (red[0] + red[1] + red[2] + red[3]) * (1.f / 512.f);
    float dx = v.x - mu, dy = v.y - mu, dz = v.z - mu, dw = v.w - mu;
    float ss = dx * dx + dy * dy + dz * dz + dw * dw;
#pragma unroll
    for (int o = 16; o; o >>= 1) ss += __shfl_xor_sync(0xffffffffu, ss, o);
    __syncthreads();
    if ((tid & 31) == 0) red[tid >> 5] = ss;
    __syncthreads();
    float var  = (red[0] + red[1] + red[2] + red[3]) * (1.f / 512.f);
    float rstd = rsqrtf(var + 1e-5f);
    float4 gg = *reinterpret_cast<const float4*>(g + tid * 4);
    float4 bb = *reinterpret_cast<const float4*>(bet + tid * 4);
    *reinterpret_cast<float4*>(outf + (size_t)row * D_ + tid * 4) =
        make_float4(dx * rstd * gg.x + bb.x, dy * rstd * gg.y + bb.y,
                    dz * rstd * gg.z + bb.z, dw * rstd * gg.w + bb.w);
}

__global__ void gather0_kernel(const float* __restrict__ h, float* __restrict__ h0)
{
    int b = blockIdx.x;
    int c = threadIdx.x * 4;
    *reinterpret_cast<float4*>(h0 + (size_t)b * D_ + c) =
        *reinterpret_cast<const float4*>(h + (size_t)b * S_ * D_ + c);
}

__global__ void cls_kernel(const float* __restrict__ pooled, const float* __restrict__ Wc1,
                           const float* __restrict__ bc1, const float* __restrict__ Wc2,
                           const float* __restrict__ bc2, float* __restrict__ out)
{
    int b = blockIdx.x;
    int j = threadIdx.x;
    __shared__ float sp[D_];
    sp[j]       = pooled[(size_t)b * D_ + j];
    sp[j + 256] = pooled[(size_t)b * D_ + j + 256];
    __syncthreads();
    float acc = bc1[j];
    for (int d = 0; d < D_; d++) acc = fmaf(sp[d], Wc1[(size_t)d * 256 + j], acc);
    float hid = acc > 0.f ? acc : 0.f;
    float p0 = hid * Wc2[j * 2 + 0];
    float p1 = hid * Wc2[j * 2 + 1];
#pragma unroll
    for (int o = 16; o; o >>= 1) {
        p0 += __shfl_xor_sync(0xffffffffu, p0, o);
        p1 += __shfl_xor_sync(0xffffffffu, p1, o);
    }
    __shared__ float r0[8], r1[8];
    if ((j & 31) == 0) { r0[j >> 5] = p0; r1[j >> 5] = p1; }
    __syncthreads();
    if (j == 0) {
        float a0 = 0.f, a1 = 0.f;
#pragma unroll
        for (int w = 0; w < 8; w++) { a0 += r0[w]; a1 += r1[w]; }
        out[b * 2 + 0] = a0 + bc2[0];
        out[b * 2 + 1] = a1 + bc2[1];
    }
}

// ================= host =================
extern "C" void kernel_launch(void* const* d_in, const int* in_sizes, int n_in,
                              void* d_out, int out_size)
{
    const int*   x   = (const int*)  d_in[0];
    const float* emb = (const float*)d_in[1];
    const float* pos = (const float*)d_in[2];
    const float* Wq  = (const float*)d_in[3];
    const float* bq  = (const float*)d_in[4];
    const float* Wk  = (const float*)d_in[5];
    const float* bk  = (const float*)d_in[6];
    const float* Wv  = (const float*)d_in[7];
    const float* bv  = (const float*)d_in[8];
    const float* P   = (const float*)d_in[9];
    const float* Wo  = (const float*)d_in[10];
    const float* bo  = (const float*)d_in[11];
    const float* lng = (const float*)d_in[12];
    const float* lnb = (const float*)d_in[13];
    const float* W1  = (const float*)d_in[14];
    const float* b1  = (const float*)d_in[15];
    const float* W2  = (const float*)d_in[16];
    const float* b2  = (const float*)d_in[17];
    const float* Wc1 = (const float*)d_in[18];
    const float* bc1 = (const float*)d_in[19];
    const float* Wc2 = (const float*)d_in[20];
    const float* bc2 = (const float*)d_in[21];
    float* out = (float*)d_out;

    float *h_, *pqk_, *kvp_, *kv_, *pks_, *pkp_, *w_, *T_, *bPQK_;
    float *s0_, *s1_, *s2_, *s3_, *sff_;
    f16 *ha_, *at_, *ln_, *ff_, *PQKh_, *PQKl_;
    f16 *Woh,*Wol_,*W1h,*W1l_,*W2h,*W2l_;
    cudaGetSymbolAddress((void**)&h_,    g_h);
    cudaGetSymbolAddress((void**)&ha_,   g_ha);
    cudaGetSymbolAddress((void**)&pqk_,  g_pqk);
    cudaGetSymbolAddress((void**)&kvp_,  g_kvpart);
    cudaGetSymbolAddress((void**)&kv_,   g_kv);
    cudaGetSymbolAddress((void**)&pks_,  g_pks);
    cudaGetSymbolAddress((void**)&pkp_,  g_pkpart);
    cudaGetSymbolAddress((void**)&at_,   g_at);
    cudaGetSymbolAddress((void**)&w_,    g_w);
    cudaGetSymbolAddress((void**)&ln_,   g_ln);
    cudaGetSymbolAddress((void**)&ff_,   g_ff);
    cudaGetSymbolAddress((void**)&T_,    g_T);
    cudaGetSymbolAddress((void**)&bPQK_, g_bPQK);
    cudaGetSymbolAddress((void**)&PQKh_, g_PQKh);
    cudaGetSymbolAddress((void**)&PQKl_, g_PQKl);
    cudaGetSymbolAddress((void**)&s0_,   g_s0);
    cudaGetSymbolAddress((void**)&s1_,   g_s1);
    cudaGetSymbolAddress((void**)&s2_,   g_s2);
    cudaGetSymbolAddress((void**)&s3_,   g_s3);
    cudaGetSymbolAddress((void**)&sff_,  g_sff);
    cudaGetSymbolAddress((void**)&Woh, g_Woh); cudaGetSymbolAddress((void**)&Wol_, g_Wolo);
    cudaGetSymbolAddress((void**)&W1h, g_W1h); cudaGetSymbolAddress((void**)&W1l_, g_W1lo);
    cudaGetSymbolAddress((void**)&W2h, g_W2h); cudaGetSymbolAddress((void**)&W2l_, g_W2lo);

    dim3 t328(32, 8);
    foldP_kernel<<<dim3(D_ / 64, 2, L_), 256>>>(Wq, Wk, P, T_);
    wsplit2_kernel<<<dim3(2, 16, 2 * L_), t328>>>(T_, PQKh_, PQKl_);
    bfold_kernel<<<dim3(L_, 2), 64>>>(bq, bk, P, bPQK_);
    wsplit_kernel<<<dim3(16, 16, L_), t328>>>(Wo, D_, D_, Woh, Wol_);
    wsplit_kernel<<<dim3(64, 16, L_), t328>>>(W1, D_, H_, W1h, W1l_);
    wsplit_kernel<<<dim3(16, 64, L_), t328>>>(W2, H_, D_, W2h, W2l_);

    embed_kernel<<<NTOK, 128>>>(x, emb, pos, h_, ha_);

    for (int l = 0; l < 3; l++) {
        const size_t dd = (size_t)l * D_ * D_;
        const size_t hd = (size_t)l * H_ * D_, dh = (size_t)l * D_ * H_;
        tcg<128, ACT_ELU1, true, false, true, false>(ha_, PQKh_ + (size_t)l * 128 * D_,
            PQKl_ + (size_t)l * 128 * D_, bPQK_ + l * 128, nullptr, pqk_, nullptr,
            NTOK, 128, D_);
        kvp_kernel<<<dim3(4, B_, NCH), 256>>>(pqk_, 128, 64, ha_, kvp_, pkp_);
        pksum_red<<<B_, 64>>>(pkp_, pks_);
        gemm_outer(kvp_, Wv + dd, pks_, bv + (size_t)l * D_, kv_);
        att_kernel<16, true><<<dim3(S_ / 16, B_), 256>>>(pqk_, 128, kv_, pks_, nullptr, at_, S_);
        tcg<128, ACT_NONE, true, false, true, false>(at_, Woh + dd, Wol_ + dd, bo + l * D_,
            nullptr, w_, nullptr, NTOK, D_, D_);
        ln_kernel<true><<<NTOK / 2, 256>>>(w_, lng + l * D_, lnb + l * D_, nullptr, ln_);
        tcg<128, ACT_GELU, true, false, false, true>(ln_, W1h + hd, W1l_ + hd, b1 + l * H_,
            nullptr, nullptr, ff_, NTOK, H_, D_);
        tcg<128, ACT_NONE, true, true, true, true>(ff_, W2h + dh, W2l_ + dh, b2 + l * D_,
            h_, h_, ha_, NTOK, D_, H_);
    }

    { // layer 3: only position 0 survives
        const int l = 3;
        const size_t dd = (size_t)l * D_ * D_, md = (size_t)l * D_ * M_;
        gather0_kernel<<<B_, 128>>>(h_, s0_);
        tcg<64, ACT_ELU1, true, false, true, false>(ha_,
            PQKh_ + (size_t)l * 128 * D_ + (size_t)64 * D_,
            PQKl_ + (size_t)l * 128 * D_ + (size_t)64 * D_,
            bPQK_ + l * 128 + 64, nullptr, pqk_, nullptr, NTOK, 64, D_);
        kvp_kernel<<<dim3(4, B_, NCH), 256>>>(pqk_, 64, 0, ha_, kvp_, pkp_);
        pksum_red<<<B_, 64>>>(pkp_, pks_);
        gemm_outer(kvp_, Wv + dd, pks_, bv + (size_t)l * D_, kv_);

        gemm128<ACT_NONE, true, false>(s0_, Wq + dd, bq + l * D_, nullptr, s1_, B_, D_, D_);
        gemm64n<ACT_ELU1>(s1_, P + md, s2_, B_, D_);
        att_kernel<1, false><<<dim3(1, B_), 256>>>(s2_, 64, kv_, pks_, s3_, nullptr, 1);
        gemm128<ACT_NONE, true, false>(s3_, Wo + dd, bo + l * D_, nullptr, s1_, B_, D_, D_);
        ln1_kernel<<<B_, 128>>>(s1_, lng + l * D_, lnb + l * D_, s3_);
        gemm128<ACT_GELU, true, false>(s3_, W1 + (size_t)l * D_ * H_, b1 + l * H_, nullptr, sff_, B_, H_, D_);
        gemm128<ACT_NONE, true, true >(sff_, W2 + (size_t)l * H_ * D_, b2 + l * D_, s0_, s1_, B_, D_, H_);
    }

    cls_kernel<<<B_, 256>>>(s1_, Wc1, bc1, Wc2, bc2, out);
}